// round 5
// baseline (speedup 1.0000x reference)
#include <cuda_runtime.h>
#include <cuda_bf16.h>

// Problem constants (fixed by the reference)
#define H 64
#define V 128
#define S 64
#define BATCH 256
#define L 4096
#define HSPLIT 4   // histogram split factor

// Scratch (no allocs allowed)
__device__ float d_hn[V * H];               // layernormed hidden per vocab id
__device__ float d_g[V * S];                // gate softmax per vocab id
__device__ float d_cnt[HSPLIT * BATCH * V]; // partial histograms (as float)

typedef unsigned long long u64;

__device__ __forceinline__ u64 pack2(float lo, float hi) {
    u64 r;
    asm("mov.b64 %0, {%1, %2};" : "=l"(r) : "f"(lo), "f"(hi));
    return r;
}
__device__ __forceinline__ void fma2(u64& d, u64 a, u64 b) {
    asm("fma.rn.f32x2 %0, %1, %2, %0;" : "+l"(d) : "l"(a), "l"(b));
}
__device__ __forceinline__ void unpack2(float& lo, float& hi, u64 v) {
    asm("mov.b64 {%0, %1}, %2;" : "=f"(lo), "=f"(hi) : "l"(v));
}

// ---------------------------------------------------------------------------
// Kernel 1: blocks [0,V) per-vocab precompute; blocks [V, V+4*BATCH) histogram
// quarters. 256 threads.
// ---------------------------------------------------------------------------
__global__ void prep_hist_kernel(const float* __restrict__ embed_w,
                                 const float* __restrict__ w1,
                                 const float* __restrict__ b1,
                                 const float* __restrict__ w2,
                                 const float* __restrict__ b2,
                                 const float* __restrict__ ln_g,
                                 const float* __restrict__ ln_b,
                                 const float* __restrict__ gate_w,
                                 const float* __restrict__ gate_b,
                                 const int* __restrict__ seq) {
    int t = threadIdx.x;
    int lane = t & 31;
    int warp = t >> 5;

    if (blockIdx.x < V) {
        // ---------------- precompute for vocab v ----------------
        int v = blockIdx.x;
        __shared__ float hs[H];
        __shared__ float us[2 * H];
        __shared__ float hns[H];
        __shared__ float wred[2][2];

        if (t < H) hs[t] = embed_w[v * H + t];
        __syncthreads();

        if (t < 2 * H) {
            float acc = b1[t];
#pragma unroll
            for (int k = 0; k < H; k++) acc = fmaf(hs[k], w1[k * (2 * H) + t], acc);
            us[t] = fmaxf(acc, 0.0f);
        }
        __syncthreads();

        float xval = 0.0f;
        if (t < H) {
            float acc = b2[t];
#pragma unroll
            for (int k = 0; k < 2 * H; k++) acc = fmaf(us[k], w2[k * H + t], acc);
            xval = hs[t] + acc;
            float s = xval, sq = xval * xval;
#pragma unroll
            for (int off = 16; off > 0; off >>= 1) {
                s  += __shfl_xor_sync(0xffffffffu, s, off);
                sq += __shfl_xor_sync(0xffffffffu, sq, off);
            }
            if (lane == 0) { wred[warp][0] = s; wred[warp][1] = sq; }
        }
        __syncthreads();

        if (t < H) {
            float s  = wred[0][0] + wred[1][0];
            float sq = wred[0][1] + wred[1][1];
            float mu = s * (1.0f / H);
            float var = sq * (1.0f / H) - mu * mu;
            float rstd = rsqrtf(var + 1e-5f);
            float val = (xval - mu) * rstd * ln_g[t] + ln_b[t];
            hns[t] = val;
            d_hn[v * H + t] = val;
        }
        __syncthreads();

        // gate softmax over S=64 (threads 0..63)
        if (t < S) {
            float l = gate_b[t];
#pragma unroll
            for (int k = 0; k < H; k++) l = fmaf(hns[k], gate_w[k * S + t], l);
            float m = l;
#pragma unroll
            for (int off = 16; off > 0; off >>= 1)
                m = fmaxf(m, __shfl_xor_sync(0xffffffffu, m, off));
            if (lane == 0) wred[warp][0] = m;
            __syncthreads();
            m = fmaxf(wred[0][0], wred[1][0]);
            float e = expf(l - m);
            float ssum = e;
#pragma unroll
            for (int off = 16; off > 0; off >>= 1)
                ssum += __shfl_xor_sync(0xffffffffu, ssum, off);
            if (lane == 0) wred[warp][1] = ssum;
            __syncthreads();
            float tot = wred[0][1] + wred[1][1];
            d_g[v * S + t] = e / tot;
        } else {
            __syncthreads();
            __syncthreads();
        }
    } else {
        // ---------------- histogram quarter c of batch b ----------------
        int id = blockIdx.x - V;
        int b = id >> 2;
        int c = id & 3;
        __shared__ int sub[8][V];
        for (int i = t; i < 8 * V; i += 256) ((int*)sub)[i] = 0;
        __syncthreads();

        // tokens [c*1024, min((c+1)*1024, L-1))
        const int4* s4 = (const int4*)(seq + b * L) + c * 256;
        int nq = (c == 3) ? 255 : 256;
        for (int i = t; i < nq; i += 256) {
            int4 x = s4[i];
            atomicAdd(&sub[warp][x.x], 1);
            atomicAdd(&sub[warp][x.y], 1);
            atomicAdd(&sub[warp][x.z], 1);
            atomicAdd(&sub[warp][x.w], 1);
        }
        if (c == 3 && t < 3) atomicAdd(&sub[warp][seq[b * L + 4092 + t]], 1);
        __syncthreads();

        if (t < V) {
            int tot = 0;
#pragma unroll
            for (int k = 0; k < 8; k++) tot += sub[k][t];
            d_cnt[(c * BATCH + b) * V + t] = (float)tot;
        }
    }
}

// ---------------------------------------------------------------------------
// Kernel 2: per-batch keys = slot_keys + sum_v c[v]*g[v] x hn[v]  (f32x2 FMAs)
// grid = BATCH, 512 threads = 4 v-groups x 128. Thread tile: 4(n) x 8(h).
// Stage 64-v half-passes in shared; register partials merged via shared.
// ---------------------------------------------------------------------------
struct FinalSmem {
    float cs[V];
    float scg[64][S];     // staged cg per half-pass; reused as reduce buf (g1)
    float shnb[64][H];    // staged hn per half-pass; reused as reduce buf (g2)
    float sredC[64][H];   // reduce buf (g3)
    float skeys[S][H + 1];
    float sq[H];
    float sattn[S];
    float sctx[H];
    float wredA[2], wredB[2], wredC2[2];
};

__global__ void __launch_bounds__(512, 2) final_kernel(
        const int* __restrict__ seq,
        const float* __restrict__ slot_keys,
        const float* __restrict__ out_w,
        const float* __restrict__ out_b,
        float* __restrict__ out) {
    extern __shared__ char smem_raw[];
    FinalSmem* sm = (FinalSmem*)smem_raw;

    int b = blockIdx.x;
    int t = threadIdx.x;   // 0..511
    int lane = t & 31;
    int warp = t >> 5;
    int tl = t & 127;      // lane within v-group
    int grp = t >> 7;      // v-group 0..3

    // counts = sum of 4 partials
    if (t < V) {
        float c = d_cnt[(0 * BATCH + b) * V + t] + d_cnt[(1 * BATCH + b) * V + t]
                + d_cnt[(2 * BATCH + b) * V + t] + d_cnt[(3 * BATCH + b) * V + t];
        sm->cs[t] = c;
    }
    __syncthreads();

    const int n0 = (tl & 15) * 4;   // 4 slot rows
    const int h0 = (tl >> 4) * 8;   // 8 h columns

    u64 acc2[4][4];
#pragma unroll
    for (int j = 0; j < 4; j++)
#pragma unroll
        for (int i = 0; i < 4; i++) acc2[j][i] = 0ULL;

#pragma unroll
    for (int pass = 0; pass < 2; pass++) {
        int vb = pass * 64;
        // stage 64 v rows of cg and hn: 1024 quads each, 512 threads
#pragma unroll
        for (int idx = t; idx < 1024; idx += 512) {
            int vv = idx >> 4;
            int n4 = (idx & 15) * 4;
            float c = sm->cs[vb + vv];
            float4 gg = *(const float4*)&d_g[(vb + vv) * S + n4];
            sm->scg[vv][n4 + 0] = gg.x * c;
            sm->scg[vv][n4 + 1] = gg.y * c;
            sm->scg[vv][n4 + 2] = gg.z * c;
            sm->scg[vv][n4 + 3] = gg.w * c;
            *(float4*)&sm->shnb[vv][n4] = *(const float4*)&d_hn[(vb + vv) * H + n4];
        }
        __syncthreads();

        int v0 = grp * 16;
#pragma unroll
        for (int k = 0; k < 16; k++) {
            int vv = v0 + k;
            u64 hv[4];
            const u64* hp = (const u64*)&sm->shnb[vv][h0];
#pragma unroll
            for (int i = 0; i < 4; i++) hv[i] = hp[i];
            float4 gq = *(const float4*)&sm->scg[vv][n0];
            u64 g2[4];
            g2[0] = pack2(gq.x, gq.x);
            g2[1] = pack2(gq.y, gq.y);
            g2[2] = pack2(gq.z, gq.z);
            g2[3] = pack2(gq.w, gq.w);
#pragma unroll
            for (int j = 0; j < 4; j++)
#pragma unroll
                for (int i = 0; i < 4; i++)
                    fma2(acc2[j][i], g2[j], hv[i]);
        }
        __syncthreads();
    }

    // merge group partials: g1->scg, g2->shnb, g3->sredC, then g0 sums + slot_keys
    if (grp != 0) {
        float (*buf)[H] = (grp == 1) ? sm->scg : (grp == 2) ? sm->shnb : sm->sredC;
#pragma unroll
        for (int j = 0; j < 4; j++) {
            float f[8];
#pragma unroll
            for (int i = 0; i < 4; i++) unpack2(f[2 * i], f[2 * i + 1], acc2[j][i]);
            *(float4*)&buf[n0 + j][h0]     = make_float4(f[0], f[1], f[2], f[3]);
            *(float4*)&buf[n0 + j][h0 + 4] = make_float4(f[4], f[5], f[6], f[7]);
        }
    }
    __syncthreads();

    if (grp == 0) {
#pragma unroll
        for (int j = 0; j < 4; j++) {
            float f[8];
#pragma unroll
            for (int i = 0; i < 4; i++) unpack2(f[2 * i], f[2 * i + 1], acc2[j][i]);
            float4 a0 = *(const float4*)&sm->scg[n0 + j][h0];
            float4 a1 = *(const float4*)&sm->scg[n0 + j][h0 + 4];
            float4 b0 = *(const float4*)&sm->shnb[n0 + j][h0];
            float4 b1 = *(const float4*)&sm->shnb[n0 + j][h0 + 4];
            float4 c0 = *(const float4*)&sm->sredC[n0 + j][h0];
            float4 c1 = *(const float4*)&sm->sredC[n0 + j][h0 + 4];
            float4 k0 = *(const float4*)&slot_keys[(n0 + j) * H + h0];
            float4 k1 = *(const float4*)&slot_keys[(n0 + j) * H + h0 + 4];
            sm->skeys[n0 + j][h0 + 0] = f[0] + a0.x + b0.x + c0.x + k0.x;
            sm->skeys[n0 + j][h0 + 1] = f[1] + a0.y + b0.y + c0.y + k0.y;
            sm->skeys[n0 + j][h0 + 2] = f[2] + a0.z + b0.z + c0.z + k0.z;
            sm->skeys[n0 + j][h0 + 3] = f[3] + a0.w + b0.w + c0.w + k0.w;
            sm->skeys[n0 + j][h0 + 4] = f[4] + a1.x + b1.x + c1.x + k1.x;
            sm->skeys[n0 + j][h0 + 5] = f[5] + a1.y + b1.y + c1.y + k1.y;
            sm->skeys[n0 + j][h0 + 6] = f[6] + a1.z + b1.z + c1.z + k1.z;
            sm->skeys[n0 + j][h0 + 7] = f[7] + a1.w + b1.w + c1.w + k1.w;
        }
    }

    // q = hn[last token]; q norm (warps 0,1)
    int qi = seq[b * L + (L - 1)];
    if (t < H) {
        float qv = d_hn[qi * H + t];
        sm->sq[t] = qv;
        float s = qv * qv;
#pragma unroll
        for (int off = 16; off > 0; off >>= 1)
            s += __shfl_xor_sync(0xffffffffu, s, off);
        if (lane == 0) sm->wredA[warp] = s;
    }
    __syncthreads();

    float simv = 0.0f;
    if (t < S) {
        float qinv = rsqrtf(fmaxf(sm->wredA[0] + sm->wredA[1], 1e-24f));
        float dot = 0.0f, nk = 0.0f;
#pragma unroll
        for (int k = 0; k < H; k++) {
            float kv = sm->skeys[t][k];
            dot = fmaf(kv, sm->sq[k], dot);
            nk = fmaf(kv, kv, nk);
        }
        simv = dot * qinv / fmaxf(sqrtf(nk), 1e-12f);
        float m = simv;
#pragma unroll
        for (int off = 16; off > 0; off >>= 1)
            m = fmaxf(m, __shfl_xor_sync(0xffffffffu, m, off));
        if (lane == 0) sm->wredB[warp] = m;
    }
    __syncthreads();

    float ev = 0.0f;
    if (t < S) {
        float m = fmaxf(sm->wredB[0], sm->wredB[1]);
        ev = expf(simv - m);
        float s = ev;
#pragma unroll
        for (int off = 16; off > 0; off >>= 1)
            s += __shfl_xor_sync(0xffffffffu, s, off);
        if (lane == 0) sm->wredC2[warp] = s;
    }
    __syncthreads();

    if (t < S) sm->sattn[t] = ev / (sm->wredC2[0] + sm->wredC2[1]);
    __syncthreads();

    if (t < H) {
        float c = 0.0f;
#pragma unroll
        for (int n = 0; n < S; n++) c = fmaf(sm->sattn[n], sm->skeys[n][t], c);
        sm->sctx[t] = c;
    }
    __syncthreads();

    // out[b, j] = ctx @ out_w + out_b (threads 0..127, 1 column each)
    if (t < V) {
        float o = out_b[t];
#pragma unroll
        for (int k = 0; k < H; k++) o = fmaf(sm->sctx[k], out_w[k * V + t], o);
        out[b * V + t] = o;
    }
}

// ---------------------------------------------------------------------------
extern "C" void kernel_launch(void* const* d_in, const int* in_sizes, int n_in,
                              void* d_out, int out_size) {
    const int*   seq       = (const int*)d_in[0];
    const float* embed_w   = (const float*)d_in[1];
    const float* w1        = (const float*)d_in[2];
    const float* b1        = (const float*)d_in[3];
    const float* w2        = (const float*)d_in[4];
    const float* b2        = (const float*)d_in[5];
    const float* ln_g      = (const float*)d_in[6];
    const float* ln_b      = (const float*)d_in[7];
    const float* slot_keys = (const float*)d_in[8];
    // d_in[9] = slot_vals (unused: reference sets vals = keys)
    const float* gate_w    = (const float*)d_in[10];
    const float* gate_b    = (const float*)d_in[11];
    const float* out_w     = (const float*)d_in[12];
    const float* out_b     = (const float*)d_in[13];
    float* out = (float*)d_out;

    int smem_bytes = (int)sizeof(FinalSmem);
    cudaFuncSetAttribute(final_kernel,
                         cudaFuncAttributeMaxDynamicSharedMemorySize, smem_bytes);

    prep_hist_kernel<<<V + HSPLIT * BATCH, 256>>>(embed_w, w1, b1, w2, b2,
                                                  ln_g, ln_b, gate_w, gate_b, seq);
    final_kernel<<<BATCH, 512, smem_bytes>>>(seq, slot_keys, out_w, out_b, out);
}